// round 13
// baseline (speedup 1.0000x reference)
#include <cuda_runtime.h>
#include <cstdint>
#include <math.h>

#define MAXG 1024
#define RESI 256
#define GSPLIT 64
#define GCHUNK 16    // MAXG / GSPLIT
#define NBLK 64      // 4 x-groups (64px) x 16 y-tiles (16px)

__device__ float4   d_g0[MAXG];                        // mx, my, cA, cB
__device__ float4   d_g1[MAXG];                        // cC, log2(op), mask(punned), 0
__device__ float    d_partial[GSPLIT * RESI * RESI];   // 16 MB scratch
__device__ unsigned d_count[NBLK];                     // zero-init; +GSPLIT per call per blk

__device__ __forceinline__ float ex2f(float x) {
    float y;
    asm("ex2.approx.ftz.f32 %0, %1;" : "=f"(y) : "f"(x));
    return y;
}

// ---------------------------------------------------------------------------
// Prep: one thread per gaussian -> conic coeffs (log2-domain) + tile bits.
// ---------------------------------------------------------------------------
__global__ void prep_kernel(const float* __restrict__ xyz,
                            const float* __restrict__ scaling,
                            const float* __restrict__ rotation,
                            const float* __restrict__ opacity,
                            const float* __restrict__ rot,
                            int N) {
    int i = blockIdx.x * blockDim.x + threadIdx.x;
    if (i >= N) return;
    const float RES = (float)RESI;

    float qr = rotation[4 * i + 0];
    float qx = rotation[4 * i + 1];
    float qy = rotation[4 * i + 2];
    float qz = rotation[4 * i + 3];
    float inv = rsqrtf(qr * qr + qx * qx + qy * qy + qz * qz);
    qr *= inv; qx *= inv; qy *= inv; qz *= inv;

    float R00 = 1.f - 2.f * (qy * qy + qz * qz);
    float R01 = 2.f * (qx * qy - qr * qz);
    float R02 = 2.f * (qx * qz + qr * qy);
    float R10 = 2.f * (qx * qy + qr * qz);
    float R11 = 1.f - 2.f * (qx * qx + qz * qz);
    float R12 = 2.f * (qy * qz - qr * qx);
    float R20 = 2.f * (qx * qz - qr * qy);
    float R21 = 2.f * (qy * qz + qr * qx);
    float R22 = 1.f - 2.f * (qx * qx + qy * qy);

    float sc0 = scaling[3 * i + 0];
    float sc1 = scaling[3 * i + 1];
    float sc2 = scaling[3 * i + 2];

    float L00 = R00 * sc0, L01 = R01 * sc1, L02 = R02 * sc2;
    float L10 = R10 * sc0, L11 = R11 * sc1, L12 = R12 * sc2;
    float L20 = R20 * sc0, L21 = R21 * sc1, L22 = R22 * sc2;

    float C00 = L00 * L00 + L01 * L01 + L02 * L02;
    float C01 = L00 * L10 + L01 * L11 + L02 * L12;
    float C02 = L00 * L20 + L01 * L21 + L02 * L22;
    float C11 = L10 * L10 + L11 * L11 + L12 * L12;
    float C12 = L10 * L20 + L11 * L21 + L12 * L22;
    float C22 = L20 * L20 + L21 * L21 + L22 * L22;

    float a00 = RES * rot[0], a01 = RES * rot[1], a02 = RES * rot[2];
    float a10 = RES * rot[3], a11 = RES * rot[4], a12 = RES * rot[5];

    float v0x = C00 * a00 + C01 * a01 + C02 * a02;
    float v0y = C01 * a00 + C11 * a01 + C12 * a02;
    float v0z = C02 * a00 + C12 * a01 + C22 * a02;
    float c00 = a00 * v0x + a01 * v0y + a02 * v0z;
    float c01 = a10 * v0x + a11 * v0y + a12 * v0z;
    float v1x = C00 * a10 + C01 * a11 + C02 * a12;
    float v1y = C01 * a10 + C11 * a11 + C12 * a12;
    float v1z = C02 * a10 + C12 * a11 + C22 * a12;
    float c11 = a10 * v1x + a11 * v1y + a12 * v1z;

    float det = c00 * c11 - c01 * c01;
    float mid = 0.5f * (c00 + c11);
    float sq = sqrtf(fmaxf(mid * mid - det, 0.1f));
    float lam = fmaxf(mid + sq, mid - sq);
    float radii = ceilf(3.0f * sqrtf(lam));

    float mx = xyz[3 * i + 0] * (RES * 0.5f);
    float my = xyz[3 * i + 1] * (RES * 0.5f);

    float rminx = fminf(fmaxf(mx - radii, 0.f), RES - 1.f);
    float rmaxx = fminf(fmaxf(mx + radii, 0.f), RES - 1.f);
    float rminy = fminf(fmaxf(my - radii, 0.f), RES - 1.f);
    float rmaxy = fminf(fmaxf(my + radii, 0.f), RES - 1.f);

    unsigned mw = 0u;
    #pragma unroll
    for (int tt = 0; tt < 16; tt++) {
        float ts = (float)(tt * 16);
        if (fminf(rmaxx, ts + 15.f) > fmaxf(rminx, ts)) mw |= (1u << tt);
        if (fminf(rmaxy, ts + 15.f) > fmaxf(rminy, ts)) mw |= (1u << (16 + tt));
    }

    float idet = 1.0f / det;
    const float L2E = 1.4426950408889634f;
    float cA = -0.5f * L2E * (c11 * idet);
    float cB = -0.5f * L2E * (c00 * idet);
    float cC = -0.5f * L2E * (-2.0f * c01 * idet);
    float lo = log2f(opacity[i]);   // fold opacity into the exponent

    d_g0[i] = make_float4(mx, my, cA, cB);
    d_g1[i] = make_float4(cC, lo, __uint_as_float(mw), 0.f);
}

// ---------------------------------------------------------------------------
// Splat: CTA = 64 threads = one 64(w) x 16(h) block (4 x-tiles, 1 y-tile),
// one GCHUNK=16 gaussian chunk. Thread t owns COLUMN x = x0+t, rows y0..y0+15.
// Per gaussian, q(y0+k) = q0 + k*d0 + k(k-1)*cB -> 2 FFMA-imm + EX2 + FADD
// per pixel; LDS + setup amortized over 16 px. x-tile exactness per thread
// via lo = bit ? log2(op) : -INF (ex2(-inf)=0).
// ---------------------------------------------------------------------------
__global__ void __launch_bounds__(64) splat_kernel(float* __restrict__ out, int N) {
    __shared__ float4 c0[GCHUNK];   // mx, my, cA, cB (compacted)
    __shared__ float4 c1[GCHUNK];   // cC, lo, xm4(punned), 0 (compacted)
    __shared__ int s_cnt;
    __shared__ unsigned s_old;

    int bid = blockIdx.x;
    int s   = bid & (GSPLIT - 1);   // gaussian split 0..63
    int blk = bid >> 6;             // pixel block 0..63
    int gx  = blk & 3;              // x-group (64 px wide)
    int gy  = blk >> 2;             // y-tile 0..15

    int g0 = s * GCHUNK;
    int gN = N - g0;
    if (gN > GCHUNK) gN = GCHUNK;
    if (gN < 0) gN = 0;

    int t = threadIdx.x;            // 0..63

    // ---- Phase 1: load + mask test + compact (warp 0, lanes 0..15 carry) ----
    if (t < 32) {
        float4 a = make_float4(0.f, 0.f, 0.f, 0.f);
        float4 b = make_float4(0.f, 0.f, 0.f, 0.f);
        bool pass = false;
        if (t < gN) {
            a = d_g0[g0 + t];
            b = d_g1[g0 + t];
            unsigned mw = __float_as_uint(b.z);
            unsigned xm4 = (mw >> (gx * 4)) & 0xFu;
            unsigned yb  = (mw >> (16 + gy)) & 1u;
            pass = (yb != 0u) && (xm4 != 0u);
            b.z = __uint_as_float(xm4);
        }
        unsigned bal = __ballot_sync(0xffffffffu, pass);
        int within = __popc(bal & ((1u << t) - 1u));
        if (pass) { c0[within] = a; c1[within] = b; }
        if (t == 0) s_cnt = __popc(bal);
    }
    __syncthreads();
    int cnt = s_cnt;

    int x  = gx * 64 + t;
    int y0 = gy * 16;
    float px = (float)x  - 127.5f;
    float py = (float)y0 - 127.5f;
    unsigned tg = (unsigned)(t >> 4);   // my x-tile within the 4-group

    float acc[16];
    #pragma unroll
    for (int k = 0; k < 16; k++) acc[k] = 0.f;

    for (int i = 0; i < cnt; i++) {
        float4 q0 = c0[i];
        float4 q1 = c1[i];
        float dx = px - q0.x;
        float dy = py - q0.y;
        float cA = q0.z;
        float cB = q0.w;
        float cC = q1.x;
        unsigned xm = __float_as_uint(q1.z);
        float lo = ((xm >> tg) & 1u) ? q1.y : -INFINITY;

        float e1 = cC * dy;
        float e2 = fmaf(cA, dx, e1);        // cA*dx + cC*dy
        float e3 = cB * dy;
        float e4 = fmaf(e3, dy, lo);        // cB*dy^2 + lo
        float qv = fmaf(dx, e2, e4);        // q(y0) + lo
        float e5 = fmaf(dy, 2.f, 1.f);      // 2*dy + 1
        float e6 = cC * dx;
        float d0 = fmaf(cB, e5, e6);        // q(y0+1) - q(y0)

        // q(y0+k) = qv + k*d0 + k(k-1)*cB   (all FFMA-imm forms)
        #pragma unroll
        for (int k = 0; k < 16; k++) {
            float qk = fmaf((float)k, d0, qv);
            qk = fmaf((float)(k * (k - 1)), cB, qk);
            acc[k] += ex2f(qk);
        }
    }

    // ---- store partial: 16 rows, coalesced STG.32 per row ----
    float* pp = &d_partial[s * (RESI * RESI) + y0 * RESI + x];
    #pragma unroll
    for (int k = 0; k < 16; k++) pp[k * RESI] = acc[k];

    // ---- Phase 3: last-CTA-per-block reduction (deterministic order) ----
    __threadfence();
    __syncthreads();
    if (t == 0) s_old = atomicAdd(&d_count[blk], 1u);
    __syncthreads();

    if (((s_old + 1) & (GSPLIT - 1)) == 0) {
        float r[16];
        #pragma unroll
        for (int k = 0; k < 16; k++) r[k] = 0.f;
        int rowoff = y0 * RESI + x;
        for (int ss = 0; ss < GSPLIT; ss++) {
            const float* p = &d_partial[ss * (RESI * RESI) + rowoff];
            #pragma unroll
            for (int k = 0; k < 16; k++) r[k] += __ldcg(&p[k * RESI]);
        }
        #pragma unroll
        for (int k = 0; k < 16; k++) out[rowoff + k * RESI] = r[k];
    }
}

// ---------------------------------------------------------------------------
extern "C" void kernel_launch(void* const* d_in, const int* in_sizes, int n_in,
                              void* d_out, int out_size) {
    const float* xyz      = (const float*)d_in[0];
    const float* scaling  = (const float*)d_in[1];
    const float* rotation = (const float*)d_in[2];
    const float* opacity  = (const float*)d_in[3];
    const float* rot      = (const float*)d_in[4];

    int N = in_sizes[0] / 3;
    if (N > MAXG) N = MAXG;

    prep_kernel<<<(N + 127) / 128, 128>>>(xyz, scaling, rotation, opacity, rot, N);
    splat_kernel<<<NBLK * GSPLIT, 64>>>((float*)d_out, N);
}

// round 14
// speedup vs baseline: 1.8582x; 1.8582x over previous
#include <cuda_runtime.h>
#include <cstdint>

#define MAXG 1024
#define RESI 256
#define GSPLIT 8
#define GCHUNK 128   // MAXG / GSPLIT
#define NTILE 256    // 16x16 tiles

__device__ float4   d_g0[MAXG];                        // mx, my, cA, cB
__device__ float4   d_g1[MAXG];                        // cC, opacity, mask(punned), 0
__device__ float    d_partial[GSPLIT * RESI * RESI];   // 2 MB scratch
__device__ unsigned d_count[NTILE];                    // zero-init; +GSPLIT per call per tile

__device__ __forceinline__ float ex2f(float x) {
    float y;
    asm("ex2.approx.ftz.f32 %0, %1;" : "=f"(y) : "f"(x));
    return y;
}

// ---------------------------------------------------------------------------
// Prep: one thread per gaussian -> conic coeffs + 16+16 tile-interval bits.
// ---------------------------------------------------------------------------
__global__ void prep_kernel(const float* __restrict__ xyz,
                            const float* __restrict__ scaling,
                            const float* __restrict__ rotation,
                            const float* __restrict__ opacity,
                            const float* __restrict__ rot,
                            int N) {
    int i = blockIdx.x * blockDim.x + threadIdx.x;
    if (i >= N) return;
    const float RES = (float)RESI;

    float qr = rotation[4 * i + 0];
    float qx = rotation[4 * i + 1];
    float qy = rotation[4 * i + 2];
    float qz = rotation[4 * i + 3];
    float inv = rsqrtf(qr * qr + qx * qx + qy * qy + qz * qz);
    qr *= inv; qx *= inv; qy *= inv; qz *= inv;

    float R00 = 1.f - 2.f * (qy * qy + qz * qz);
    float R01 = 2.f * (qx * qy - qr * qz);
    float R02 = 2.f * (qx * qz + qr * qy);
    float R10 = 2.f * (qx * qy + qr * qz);
    float R11 = 1.f - 2.f * (qx * qx + qz * qz);
    float R12 = 2.f * (qy * qz - qr * qx);
    float R20 = 2.f * (qx * qz - qr * qy);
    float R21 = 2.f * (qy * qz + qr * qx);
    float R22 = 1.f - 2.f * (qx * qx + qy * qy);

    float sc0 = scaling[3 * i + 0];
    float sc1 = scaling[3 * i + 1];
    float sc2 = scaling[3 * i + 2];

    float L00 = R00 * sc0, L01 = R01 * sc1, L02 = R02 * sc2;
    float L10 = R10 * sc0, L11 = R11 * sc1, L12 = R12 * sc2;
    float L20 = R20 * sc0, L21 = R21 * sc1, L22 = R22 * sc2;

    float C00 = L00 * L00 + L01 * L01 + L02 * L02;
    float C01 = L00 * L10 + L01 * L11 + L02 * L12;
    float C02 = L00 * L20 + L01 * L21 + L02 * L22;
    float C11 = L10 * L10 + L11 * L11 + L12 * L12;
    float C12 = L10 * L20 + L11 * L21 + L12 * L22;
    float C22 = L20 * L20 + L21 * L21 + L22 * L22;

    float a00 = RES * rot[0], a01 = RES * rot[1], a02 = RES * rot[2];
    float a10 = RES * rot[3], a11 = RES * rot[4], a12 = RES * rot[5];

    float v0x = C00 * a00 + C01 * a01 + C02 * a02;
    float v0y = C01 * a00 + C11 * a01 + C12 * a02;
    float v0z = C02 * a00 + C12 * a01 + C22 * a02;
    float c00 = a00 * v0x + a01 * v0y + a02 * v0z;
    float c01 = a10 * v0x + a11 * v0y + a12 * v0z;
    float v1x = C00 * a10 + C01 * a11 + C02 * a12;
    float v1y = C01 * a10 + C11 * a11 + C12 * a12;
    float v1z = C02 * a10 + C12 * a11 + C22 * a12;
    float c11 = a10 * v1x + a11 * v1y + a12 * v1z;

    float det = c00 * c11 - c01 * c01;
    float mid = 0.5f * (c00 + c11);
    float sq = sqrtf(fmaxf(mid * mid - det, 0.1f));
    float lam = fmaxf(mid + sq, mid - sq);
    float radii = ceilf(3.0f * sqrtf(lam));

    float mx = xyz[3 * i + 0] * (RES * 0.5f);
    float my = xyz[3 * i + 1] * (RES * 0.5f);

    float rminx = fminf(fmaxf(mx - radii, 0.f), RES - 1.f);
    float rmaxx = fminf(fmaxf(mx + radii, 0.f), RES - 1.f);
    float rminy = fminf(fmaxf(my - radii, 0.f), RES - 1.f);
    float rmaxy = fminf(fmaxf(my + radii, 0.f), RES - 1.f);

    unsigned mw = 0u;
    #pragma unroll
    for (int tt = 0; tt < 16; tt++) {
        float ts = (float)(tt * 16);
        if (fminf(rmaxx, ts + 15.f) > fmaxf(rminx, ts)) mw |= (1u << tt);
        if (fminf(rmaxy, ts + 15.f) > fmaxf(rminy, ts)) mw |= (1u << (16 + tt));
    }

    float idet = 1.0f / det;
    const float L2E = 1.4426950408889634f;
    float cA = -0.5f * L2E * (c11 * idet);
    float cB = -0.5f * L2E * (c00 * idet);
    float cC = -0.5f * L2E * (-2.0f * c01 * idet);

    d_g0[i] = make_float4(mx, my, cA, cB);
    d_g1[i] = make_float4(cC, opacity[i], __uint_as_float(mw), 0.f);
}

// ---------------------------------------------------------------------------
// Splat: one CTA = one 16x16 tile x one interleaved 128-gaussian chunk,
// 64 threads, 4 px/thread. Chunk s = gaussians {s, s+8, s+16, ...} so cnt is
// balanced across the 8 splits of each tile. Inner loop = proven R11 form.
// ---------------------------------------------------------------------------
__global__ void __launch_bounds__(64) splat_kernel(float* __restrict__ out, int N) {
    __shared__ float4 c0[GCHUNK];         // mx, my, cA, cB (compacted)
    __shared__ float2 c1[GCHUNK];         // cC, opacity    (compacted)
    __shared__ int    s_cnt4[4];          // counts: (round, warp) = r*2+w
    __shared__ unsigned s_old;

    int bid = blockIdx.x;
    int s   = bid & (GSPLIT - 1);   // gaussian split 0..7
    int blk = bid >> 3;             // tile 0..255
    int bx  = blk & 15;             // tile column
    int ty  = blk >> 4;             // tile row

    int t    = threadIdx.x;         // 0..63
    int lane = t & 31;
    int wid  = t >> 5;

    // ---- Phase 1: load 2 interleaved gaussians/thread + mask + compact ----
    float4 q0a = make_float4(0.f, 0.f, 0.f, 0.f), q0b = q0a;
    float4 q1a = q0a, q1b = q0a;
    bool pa = false, pb = false;
    {
        int ga = s + GSPLIT * t;            // j = t     (0..63)
        int gb = s + GSPLIT * (t + 64);     // j = t+64  (64..127)
        if (ga < N) {
            q0a = d_g0[ga]; q1a = d_g1[ga];
            unsigned mw = __float_as_uint(q1a.z);
            pa = ((mw >> bx) & (mw >> (16 + ty)) & 1u) != 0u;
        }
        if (gb < N) {
            q0b = d_g0[gb]; q1b = d_g1[gb];
            unsigned mw = __float_as_uint(q1b.z);
            pb = ((mw >> bx) & (mw >> (16 + ty)) & 1u) != 0u;
        }
    }
    unsigned balA = __ballot_sync(0xffffffffu, pa);
    unsigned balB = __ballot_sync(0xffffffffu, pb);
    if (lane == 0) {
        s_cnt4[wid]     = __popc(balA);
        s_cnt4[2 + wid] = __popc(balB);
    }
    __syncthreads();
    int cA0 = s_cnt4[0], cA1 = s_cnt4[1], cB0 = s_cnt4[2], cB1 = s_cnt4[3];
    int cnt = cA0 + cA1 + cB0 + cB1;
    // stable order: roundA warp0, roundA warp1, roundB warp0, roundB warp1
    int baseA = (wid == 1) ? cA0 : 0;
    int baseB = cA0 + cA1 + ((wid == 1) ? cB0 : 0);
    int wA = __popc(balA & ((1u << lane) - 1u));
    int wB = __popc(balB & ((1u << lane) - 1u));
    if (pa) {
        int p = baseA + wA;
        c0[p] = q0a;
        c1[p] = make_float2(q1a.x, q1a.y);
    }
    if (pb) {
        int p = baseB + wB;
        c0[p] = q0b;
        c1[p] = make_float2(q1b.x, q1b.y);
    }
    __syncthreads();

    // ---- Phase 2: dense branch-free splat, 4 px per thread (one row) ----
    int cg  = t & 3;
    int row = t >> 2;               // 0..15
    int x = bx * 16 + cg * 4;
    int y = ty * 16 + row;

    float px = (float)x - 127.5f;
    float py = (float)y - 127.5f;

    float a0 = 0.f, a1 = 0.f, a2 = 0.f, a3 = 0.f;

    #pragma unroll 2
    for (int i = 0; i < cnt; i++) {
        float4 q0 = c0[i];
        float2 q1 = c1[i];
        float dx = px - q0.x;
        float dy = py - q0.y;
        float cAi = q0.z;
        float h  = q1.x * dy;               // cC * dy
        float sB = q0.w * (dy * dy);        // cB * dy^2
        float o  = q1.y;

        float inner = fmaf(cAi, dx, h);     // cA*dx + h
        float g     = fmaf(cAi, dx, inner); // 2*cA*dx + h
        float base  = fmaf(dx, inner, sB);  // q(0)

        float w0 = ex2f(base);
        float w1 = ex2f(fmaf(1.f, cAi, fmaf(1.f, g, base)));
        float w2 = ex2f(fmaf(4.f, cAi, fmaf(2.f, g, base)));
        float w3 = ex2f(fmaf(9.f, cAi, fmaf(3.f, g, base)));

        a0 = fmaf(w0, o, a0);
        a1 = fmaf(w1, o, a1);
        a2 = fmaf(w2, o, a2);
        a3 = fmaf(w3, o, a3);
    }

    int pix = y * RESI + x;
    *reinterpret_cast<float4*>(&d_partial[s * (RESI * RESI) + pix]) =
        make_float4(a0, a1, a2, a3);

    // ---- Phase 3: last-CTA-per-tile reduction (deterministic order) ----
    __threadfence();
    __syncthreads();
    if (t == 0) s_old = atomicAdd(&d_count[blk], 1u);
    __syncthreads();

    if (((s_old + 1) & (GSPLIT - 1)) == 0) {
        const float4* p = reinterpret_cast<const float4*>(d_partial);
        int idx = pix >> 2;
        float4 a = __ldcg(&p[idx]);
        #pragma unroll
        for (int ss = 1; ss < GSPLIT; ss++) {
            float4 b = __ldcg(&p[ss * (RESI * RESI / 4) + idx]);
            a.x += b.x; a.y += b.y; a.z += b.z; a.w += b.w;
        }
        *reinterpret_cast<float4*>(&out[pix]) = a;
    }
}

// ---------------------------------------------------------------------------
extern "C" void kernel_launch(void* const* d_in, const int* in_sizes, int n_in,
                              void* d_out, int out_size) {
    const float* xyz      = (const float*)d_in[0];
    const float* scaling  = (const float*)d_in[1];
    const float* rotation = (const float*)d_in[2];
    const float* opacity  = (const float*)d_in[3];
    const float* rot      = (const float*)d_in[4];

    int N = in_sizes[0] / 3;
    if (N > MAXG) N = MAXG;

    prep_kernel<<<(N + 127) / 128, 128>>>(xyz, scaling, rotation, opacity, rot, N);
    splat_kernel<<<NTILE * GSPLIT, 64>>>((float*)d_out, N);
}

// round 15
// speedup vs baseline: 2.1549x; 1.1597x over previous
#include <cuda_runtime.h>
#include <cstdint>

#define MAXG 1024
#define RESI 256
#define GSPLIT 16
#define GCHUNK 64    // MAXG / GSPLIT
#define NTILE 256    // 16x16 tiles

__device__ float4   d_g0[MAXG];                        // mx, my, cA, cB
__device__ float4   d_g1[MAXG];                        // cC, opacity, mask(punned), f=ex2(2cA)
__device__ float    d_partial[GSPLIT * RESI * RESI];   // 4 MB scratch
__device__ unsigned d_count[NTILE];                    // zero-init; +GSPLIT per call per tile

__device__ __forceinline__ float ex2f(float x) {
    float y;
    asm("ex2.approx.ftz.f32 %0, %1;" : "=f"(y) : "f"(x));
    return y;
}

// ---------------------------------------------------------------------------
// Prep: one thread per gaussian -> conic coeffs + tile bits + ratio constant.
// ---------------------------------------------------------------------------
__global__ void prep_kernel(const float* __restrict__ xyz,
                            const float* __restrict__ scaling,
                            const float* __restrict__ rotation,
                            const float* __restrict__ opacity,
                            const float* __restrict__ rot,
                            int N) {
    int i = blockIdx.x * blockDim.x + threadIdx.x;
    if (i >= N) return;
    const float RES = (float)RESI;

    float qr = rotation[4 * i + 0];
    float qx = rotation[4 * i + 1];
    float qy = rotation[4 * i + 2];
    float qz = rotation[4 * i + 3];
    float inv = rsqrtf(qr * qr + qx * qx + qy * qy + qz * qz);
    qr *= inv; qx *= inv; qy *= inv; qz *= inv;

    float R00 = 1.f - 2.f * (qy * qy + qz * qz);
    float R01 = 2.f * (qx * qy - qr * qz);
    float R02 = 2.f * (qx * qz + qr * qy);
    float R10 = 2.f * (qx * qy + qr * qz);
    float R11 = 1.f - 2.f * (qx * qx + qz * qz);
    float R12 = 2.f * (qy * qz - qr * qx);
    float R20 = 2.f * (qx * qz - qr * qy);
    float R21 = 2.f * (qy * qz + qr * qx);
    float R22 = 1.f - 2.f * (qx * qx + qy * qy);

    float sc0 = scaling[3 * i + 0];
    float sc1 = scaling[3 * i + 1];
    float sc2 = scaling[3 * i + 2];

    float L00 = R00 * sc0, L01 = R01 * sc1, L02 = R02 * sc2;
    float L10 = R10 * sc0, L11 = R11 * sc1, L12 = R12 * sc2;
    float L20 = R20 * sc0, L21 = R21 * sc1, L22 = R22 * sc2;

    float C00 = L00 * L00 + L01 * L01 + L02 * L02;
    float C01 = L00 * L10 + L01 * L11 + L02 * L12;
    float C02 = L00 * L20 + L01 * L21 + L02 * L22;
    float C11 = L10 * L10 + L11 * L11 + L12 * L12;
    float C12 = L10 * L20 + L11 * L21 + L12 * L22;
    float C22 = L20 * L20 + L21 * L21 + L22 * L22;

    float a00 = RES * rot[0], a01 = RES * rot[1], a02 = RES * rot[2];
    float a10 = RES * rot[3], a11 = RES * rot[4], a12 = RES * rot[5];

    float v0x = C00 * a00 + C01 * a01 + C02 * a02;
    float v0y = C01 * a00 + C11 * a01 + C12 * a02;
    float v0z = C02 * a00 + C12 * a01 + C22 * a02;
    float c00 = a00 * v0x + a01 * v0y + a02 * v0z;
    float c01 = a10 * v0x + a11 * v0y + a12 * v0z;
    float v1x = C00 * a10 + C01 * a11 + C02 * a12;
    float v1y = C01 * a10 + C11 * a11 + C12 * a12;
    float v1z = C02 * a10 + C12 * a11 + C22 * a12;
    float c11 = a10 * v1x + a11 * v1y + a12 * v1z;

    float det = c00 * c11 - c01 * c01;
    float mid = 0.5f * (c00 + c11);
    float sq = sqrtf(fmaxf(mid * mid - det, 0.1f));
    float lam = fmaxf(mid + sq, mid - sq);
    float radii = ceilf(3.0f * sqrtf(lam));

    float mx = xyz[3 * i + 0] * (RES * 0.5f);
    float my = xyz[3 * i + 1] * (RES * 0.5f);

    float rminx = fminf(fmaxf(mx - radii, 0.f), RES - 1.f);
    float rmaxx = fminf(fmaxf(mx + radii, 0.f), RES - 1.f);
    float rminy = fminf(fmaxf(my - radii, 0.f), RES - 1.f);
    float rmaxy = fminf(fmaxf(my + radii, 0.f), RES - 1.f);

    unsigned mw = 0u;
    #pragma unroll
    for (int tt = 0; tt < 16; tt++) {
        float ts = (float)(tt * 16);
        if (fminf(rmaxx, ts + 15.f) > fmaxf(rminx, ts)) mw |= (1u << tt);
        if (fminf(rmaxy, ts + 15.f) > fmaxf(rminy, ts)) mw |= (1u << (16 + tt));
    }

    float idet = 1.0f / det;
    const float L2E = 1.4426950408889634f;
    float cA = -0.5f * L2E * (c11 * idet);
    float cB = -0.5f * L2E * (c00 * idet);
    float cC = -0.5f * L2E * (-2.0f * c01 * idet);
    float f  = ex2f(2.0f * cA);      // constant second-difference ratio (<=1)

    d_g0[i] = make_float4(mx, my, cA, cB);
    d_g1[i] = make_float4(cC, opacity[i], __uint_as_float(mw), f);
}

// ---------------------------------------------------------------------------
// Splat: one CTA = one 16x16 tile x one 64-gaussian chunk, 64 threads,
// 4 px/thread. R11 layout; inner loop uses the geometric-ratio form:
//   w0 = ex2(q0), r0 = ex2(g+cA) (clamped), ratio multiplies by f each step.
// 2 EX2 per iteration instead of 4.
// ---------------------------------------------------------------------------
__global__ void __launch_bounds__(64) splat_kernel(float* __restrict__ out, int N) {
    __shared__ float4 c0[GCHUNK];         // mx, my, cA, cB (compacted)
    __shared__ float4 c1[GCHUNK];         // cC, opacity, f, 0 (compacted)
    __shared__ int    s_warpcnt[2];
    __shared__ unsigned s_old;

    int bid = blockIdx.x;
    int s   = bid & (GSPLIT - 1);   // gaussian split
    int blk = bid >> 4;             // tile 0..255
    int bx  = blk & 15;             // tile column
    int ty  = blk >> 4;             // tile row

    int g0 = s * GCHUNK;
    int gN = N - g0;
    if (gN > GCHUNK) gN = GCHUNK;
    if (gN < 0) gN = 0;

    int t    = threadIdx.x;         // 0..63
    int lane = t & 31;
    int wid  = t >> 5;

    // ---- Phase 1: load precomputed params + mask test + compact ----
    float4 q0v = make_float4(0.f, 0.f, 0.f, 0.f);
    float4 q1v = make_float4(0.f, 0.f, 0.f, 0.f);
    bool pass = false;
    if (t < gN) {
        q0v = d_g0[g0 + t];
        q1v = d_g1[g0 + t];
        unsigned mw = __float_as_uint(q1v.z);
        pass = ((mw >> bx) & (mw >> (16 + ty)) & 1u) != 0u;
    }

    unsigned bal = __ballot_sync(0xffffffffu, pass);
    int within = __popc(bal & ((1u << lane) - 1u));
    if (lane == 0) s_warpcnt[wid] = __popc(bal);
    __syncthreads();
    int base_off = (wid == 1) ? s_warpcnt[0] : 0;
    int cnt = s_warpcnt[0] + s_warpcnt[1];
    if (pass) {
        int p = base_off + within;
        c0[p] = q0v;
        c1[p] = make_float4(q1v.x, q1v.y, q1v.w, 0.f);
    }
    __syncthreads();

    // ---- Phase 2: dense branch-free splat, 4 px per thread (one row) ----
    int cg  = t & 3;
    int row = t >> 2;               // 0..15
    int x = bx * 16 + cg * 4;
    int y = ty * 16 + row;

    float px = (float)x - 127.5f;
    float py = (float)y - 127.5f;

    float a0 = 0.f, a1 = 0.f, a2 = 0.f, a3 = 0.f;

    #pragma unroll 2
    for (int i = 0; i < cnt; i++) {
        float4 q0 = c0[i];
        float4 q1 = c1[i];
        float dx = px - q0.x;
        float dy = py - q0.y;
        float cAi = q0.z;
        float h  = q1.x * dy;               // cC * dy
        float sB = q0.w * (dy * dy);        // cB * dy^2
        float o  = q1.y;
        float f  = q1.z;                    // ex2(2*cA), <= 1

        float inner = fmaf(cAi, dx, h);     // cA*dx + h
        float g     = fmaf(cAi, dx, inner); // 2*cA*dx + h
        float base  = fmaf(dx, inner, sB);  // q(0)

        float w0 = ex2f(base);
        float r0 = fminf(ex2f(g + cAi), 1e30f);  // q(1)-q(0); clamp kills 0*inf
        float r1 = r0 * f;                       // q(2)-q(1) ratio
        float r2 = r1 * f;                       // q(3)-q(2) ratio
        float w1 = w0 * r0;
        float w2 = w1 * r1;
        float w3 = w2 * r2;

        a0 = fmaf(w0, o, a0);
        a1 = fmaf(w1, o, a1);
        a2 = fmaf(w2, o, a2);
        a3 = fmaf(w3, o, a3);
    }

    int pix = y * RESI + x;
    *reinterpret_cast<float4*>(&d_partial[s * (RESI * RESI) + pix]) =
        make_float4(a0, a1, a2, a3);

    // ---- Phase 3: last-CTA-per-tile reduction (deterministic order) ----
    __threadfence();
    __syncthreads();
    if (t == 0) s_old = atomicAdd(&d_count[blk], 1u);
    __syncthreads();

    if (((s_old + 1) & (GSPLIT - 1)) == 0) {
        const float4* p = reinterpret_cast<const float4*>(d_partial);
        int idx = pix >> 2;
        float4 a = __ldcg(&p[idx]);
        #pragma unroll
        for (int ss = 1; ss < GSPLIT; ss++) {
            float4 b = __ldcg(&p[ss * (RESI * RESI / 4) + idx]);
            a.x += b.x; a.y += b.y; a.z += b.z; a.w += b.w;
        }
        *reinterpret_cast<float4*>(&out[pix]) = a;
    }
}

// ---------------------------------------------------------------------------
extern "C" void kernel_launch(void* const* d_in, const int* in_sizes, int n_in,
                              void* d_out, int out_size) {
    const float* xyz      = (const float*)d_in[0];
    const float* scaling  = (const float*)d_in[1];
    const float* rotation = (const float*)d_in[2];
    const float* opacity  = (const float*)d_in[3];
    const float* rot      = (const float*)d_in[4];

    int N = in_sizes[0] / 3;
    if (N > MAXG) N = MAXG;

    prep_kernel<<<(N + 127) / 128, 128>>>(xyz, scaling, rotation, opacity, rot, N);
    splat_kernel<<<NTILE * GSPLIT, 64>>>((float*)d_out, N);
}

// round 16
// speedup vs baseline: 2.3342x; 1.0832x over previous
#include <cuda_runtime.h>
#include <cstdint>

#define MAXG 1024
#define RESI 256
#define GSPLIT 16
#define GCHUNK 64    // MAXG / GSPLIT
#define NTILE 256    // 16x16 tiles

__device__ float4   d_g0[MAXG];                        // mx, my, cA, cB
__device__ float4   d_g1[MAXG];                        // cC, opacity, mask(punned), f=ex2(2cA)
__device__ float    d_partial[GSPLIT * RESI * RESI];   // 4 MB scratch
__device__ unsigned d_count[NTILE];                    // zero-init; +GSPLIT per call per tile

__device__ __forceinline__ float ex2f(float x) {
    float y;
    asm("ex2.approx.ftz.f32 %0, %1;" : "=f"(y) : "f"(x));
    return y;
}

// ---------------------------------------------------------------------------
// Prep: one thread per gaussian -> conic coeffs + tile bits + ratio constant.
// ---------------------------------------------------------------------------
__global__ void prep_kernel(const float* __restrict__ xyz,
                            const float* __restrict__ scaling,
                            const float* __restrict__ rotation,
                            const float* __restrict__ opacity,
                            const float* __restrict__ rot,
                            int N) {
    int i = blockIdx.x * blockDim.x + threadIdx.x;
    if (i >= N) return;
    const float RES = (float)RESI;

    float qr = rotation[4 * i + 0];
    float qx = rotation[4 * i + 1];
    float qy = rotation[4 * i + 2];
    float qz = rotation[4 * i + 3];
    float inv = rsqrtf(qr * qr + qx * qx + qy * qy + qz * qz);
    qr *= inv; qx *= inv; qy *= inv; qz *= inv;

    float R00 = 1.f - 2.f * (qy * qy + qz * qz);
    float R01 = 2.f * (qx * qy - qr * qz);
    float R02 = 2.f * (qx * qz + qr * qy);
    float R10 = 2.f * (qx * qy + qr * qz);
    float R11 = 1.f - 2.f * (qx * qx + qz * qz);
    float R12 = 2.f * (qy * qz - qr * qx);
    float R20 = 2.f * (qx * qz - qr * qy);
    float R21 = 2.f * (qy * qz + qr * qx);
    float R22 = 1.f - 2.f * (qx * qx + qy * qy);

    float sc0 = scaling[3 * i + 0];
    float sc1 = scaling[3 * i + 1];
    float sc2 = scaling[3 * i + 2];

    float L00 = R00 * sc0, L01 = R01 * sc1, L02 = R02 * sc2;
    float L10 = R10 * sc0, L11 = R11 * sc1, L12 = R12 * sc2;
    float L20 = R20 * sc0, L21 = R21 * sc1, L22 = R22 * sc2;

    float C00 = L00 * L00 + L01 * L01 + L02 * L02;
    float C01 = L00 * L10 + L01 * L11 + L02 * L12;
    float C02 = L00 * L20 + L01 * L21 + L02 * L22;
    float C11 = L10 * L10 + L11 * L11 + L12 * L12;
    float C12 = L10 * L20 + L11 * L21 + L12 * L22;
    float C22 = L20 * L20 + L21 * L21 + L22 * L22;

    float a00 = RES * rot[0], a01 = RES * rot[1], a02 = RES * rot[2];
    float a10 = RES * rot[3], a11 = RES * rot[4], a12 = RES * rot[5];

    float v0x = C00 * a00 + C01 * a01 + C02 * a02;
    float v0y = C01 * a00 + C11 * a01 + C12 * a02;
    float v0z = C02 * a00 + C12 * a01 + C22 * a02;
    float c00 = a00 * v0x + a01 * v0y + a02 * v0z;
    float c01 = a10 * v0x + a11 * v0y + a12 * v0z;
    float v1x = C00 * a10 + C01 * a11 + C02 * a12;
    float v1y = C01 * a10 + C11 * a11 + C12 * a12;
    float v1z = C02 * a10 + C12 * a11 + C22 * a12;
    float c11 = a10 * v1x + a11 * v1y + a12 * v1z;

    float det = c00 * c11 - c01 * c01;
    float mid = 0.5f * (c00 + c11);
    float sq = sqrtf(fmaxf(mid * mid - det, 0.1f));
    float lam = fmaxf(mid + sq, mid - sq);
    float radii = ceilf(3.0f * sqrtf(lam));

    float mx = xyz[3 * i + 0] * (RES * 0.5f);
    float my = xyz[3 * i + 1] * (RES * 0.5f);

    float rminx = fminf(fmaxf(mx - radii, 0.f), RES - 1.f);
    float rmaxx = fminf(fmaxf(mx + radii, 0.f), RES - 1.f);
    float rminy = fminf(fmaxf(my - radii, 0.f), RES - 1.f);
    float rmaxy = fminf(fmaxf(my + radii, 0.f), RES - 1.f);

    unsigned mw = 0u;
    #pragma unroll
    for (int tt = 0; tt < 16; tt++) {
        float ts = (float)(tt * 16);
        if (fminf(rmaxx, ts + 15.f) > fmaxf(rminx, ts)) mw |= (1u << tt);
        if (fminf(rmaxy, ts + 15.f) > fmaxf(rminy, ts)) mw |= (1u << (16 + tt));
    }

    float idet = 1.0f / det;
    const float L2E = 1.4426950408889634f;
    float cA = -0.5f * L2E * (c11 * idet);
    float cB = -0.5f * L2E * (c00 * idet);
    float cC = -0.5f * L2E * (-2.0f * c01 * idet);
    float f  = ex2f(2.0f * cA);      // constant second-difference ratio (<=1)

    d_g0[i] = make_float4(mx, my, cA, cB);
    d_g1[i] = make_float4(cC, opacity[i], __uint_as_float(mw), f);
}

// ---------------------------------------------------------------------------
// Splat: one CTA = ONE WARP = one 16x16 tile x one 64-gaussian chunk.
// Thread t owns 8 px of row t>>1 (half = t&1). Geometric-ratio chain:
// 2 EX2 + 13 FMUL + 8 FFMA per 8 pixels; setup amortized over 8 px.
// ---------------------------------------------------------------------------
__global__ void __launch_bounds__(32) splat_kernel(float* __restrict__ out, int N) {
    __shared__ float4 c0[GCHUNK];         // mx, my, cA, cB (compacted)
    __shared__ float4 c1[GCHUNK];         // cC, opacity, f, 0 (compacted)

    int bid = blockIdx.x;
    int s   = bid & (GSPLIT - 1);   // gaussian split
    int blk = bid >> 4;             // tile 0..255
    int bx  = blk & 15;             // tile column
    int ty  = blk >> 4;             // tile row

    int g0 = s * GCHUNK;
    int gN = N - g0;
    if (gN > GCHUNK) gN = GCHUNK;
    if (gN < 0) gN = 0;

    int t = threadIdx.x;            // 0..31 (one warp)

    // ---- Phase 1: two-round load + mask test + compact (single warp) ----
    float4 q0a, q1a, q0b, q1b;
    bool pa = false, pb = false;
    {
        int ga = g0 + t;
        int gb = g0 + t + 32;
        if (t < gN) {
            q0a = d_g0[ga]; q1a = d_g1[ga];
            unsigned mw = __float_as_uint(q1a.z);
            pa = ((mw >> bx) & (mw >> (16 + ty)) & 1u) != 0u;
        }
        if (t + 32 < gN) {
            q0b = d_g0[gb]; q1b = d_g1[gb];
            unsigned mw = __float_as_uint(q1b.z);
            pb = ((mw >> bx) & (mw >> (16 + ty)) & 1u) != 0u;
        }
    }
    unsigned balA = __ballot_sync(0xffffffffu, pa);
    unsigned balB = __ballot_sync(0xffffffffu, pb);
    unsigned ltm  = (1u << t) - 1u;
    int cA_ = __popc(balA);
    int cnt = cA_ + __popc(balB);
    if (pa) {
        int p = __popc(balA & ltm);
        c0[p] = q0a;
        c1[p] = make_float4(q1a.x, q1a.y, q1a.w, 0.f);
    }
    if (pb) {
        int p = cA_ + __popc(balB & ltm);
        c0[p] = q0b;
        c1[p] = make_float4(q1b.x, q1b.y, q1b.w, 0.f);
    }
    __syncwarp();

    // ---- Phase 2: dense splat, 8 px per thread (half of one row) ----
    int row  = t >> 1;              // 0..15
    int half = t & 1;               // 0 or 1
    int x = bx * 16 + half * 8;
    int y = ty * 16 + row;

    float px = (float)x - 127.5f;
    float py = (float)y - 127.5f;

    float a0 = 0.f, a1 = 0.f, a2 = 0.f, a3 = 0.f;
    float a4 = 0.f, a5 = 0.f, a6 = 0.f, a7 = 0.f;

    #pragma unroll 2
    for (int i = 0; i < cnt; i++) {
        float4 q0 = c0[i];
        float4 q1 = c1[i];
        float dx = px - q0.x;
        float dy = py - q0.y;
        float cAi = q0.z;
        float h  = q1.x * dy;               // cC * dy
        float sB = q0.w * (dy * dy);        // cB * dy^2
        float o  = q1.y;
        float f  = q1.z;                    // ex2(2*cA), <= 1

        float inner = fmaf(cAi, dx, h);     // cA*dx + h
        float g     = fmaf(cAi, dx, inner); // 2*cA*dx + h
        float base  = fmaf(dx, inner, sB);  // q(0)

        float w0 = ex2f(base);
        float r  = fminf(ex2f(g + cAi), 1e30f);  // ratio w1/w0; clamp kills 0*inf
        float w1 = w0 * r;  r *= f;
        float w2 = w1 * r;  r *= f;
        float w3 = w2 * r;  r *= f;
        float w4 = w3 * r;  r *= f;
        float w5 = w4 * r;  r *= f;
        float w6 = w5 * r;  r *= f;
        float w7 = w6 * r;

        a0 = fmaf(w0, o, a0);
        a1 = fmaf(w1, o, a1);
        a2 = fmaf(w2, o, a2);
        a3 = fmaf(w3, o, a3);
        a4 = fmaf(w4, o, a4);
        a5 = fmaf(w5, o, a5);
        a6 = fmaf(w6, o, a6);
        a7 = fmaf(w7, o, a7);
    }

    int pix = y * RESI + x;
    float4* pp = reinterpret_cast<float4*>(&d_partial[s * (RESI * RESI) + pix]);
    pp[0] = make_float4(a0, a1, a2, a3);
    pp[1] = make_float4(a4, a5, a6, a7);

    // ---- Phase 3: last-CTA-per-tile reduction (deterministic order) ----
    __threadfence();
    unsigned old = 0u;
    if (t == 0) old = atomicAdd(&d_count[blk], 1u);
    old = __shfl_sync(0xffffffffu, old, 0);

    if (((old + 1) & (GSPLIT - 1)) == 0) {
        const float4* p = reinterpret_cast<const float4*>(d_partial);
        int idx = pix >> 2;                     // my first float4
        float4 r0 = __ldcg(&p[idx]);
        float4 r1 = __ldcg(&p[idx + 1]);
        #pragma unroll
        for (int ss = 1; ss < GSPLIT; ss++) {
            const float4* q = &p[ss * (RESI * RESI / 4)];
            float4 b0 = __ldcg(&q[idx]);
            float4 b1 = __ldcg(&q[idx + 1]);
            r0.x += b0.x; r0.y += b0.y; r0.z += b0.z; r0.w += b0.w;
            r1.x += b1.x; r1.y += b1.y; r1.z += b1.z; r1.w += b1.w;
        }
        float4* po = reinterpret_cast<float4*>(&out[pix]);
        po[0] = r0;
        po[1] = r1;
    }
}

// ---------------------------------------------------------------------------
extern "C" void kernel_launch(void* const* d_in, const int* in_sizes, int n_in,
                              void* d_out, int out_size) {
    const float* xyz      = (const float*)d_in[0];
    const float* scaling  = (const float*)d_in[1];
    const float* rotation = (const float*)d_in[2];
    const float* opacity  = (const float*)d_in[3];
    const float* rot      = (const float*)d_in[4];

    int N = in_sizes[0] / 3;
    if (N > MAXG) N = MAXG;

    prep_kernel<<<(N + 127) / 128, 128>>>(xyz, scaling, rotation, opacity, rot, N);
    splat_kernel<<<NTILE * GSPLIT, 32>>>((float*)d_out, N);
}